// round 15
// baseline (speedup 1.0000x reference)
#include <cuda_runtime.h>
#include <cuda_fp16.h>

// SpatialTransformer3D: batched 3D trilinear sampling.
//
// Prepass packs the image into fp16 x-pair patches, 2 parity copies:
//   patch(b,sx,y,px,z) = { img[y, 2px+sx, z], img[y, min(2px+sx+1,127), z] }
//   = 8 halves = 16B. Packed total 67MB.
// Main kernel: lane bit0 = z-corner select; pair lanes load patches at
// z0 / z0+1 (16B apart -> same 128B line) -> 2 distinct 128B lines per
// voxel (minimal for <=67MB packing). trans/out use streaming hints so
// the packed array keeps L2. Serial schedule (overlap loses: R12/R13).
// launch_bounds(256,6) pins 48 warps/SM to cover L1tex latency bubbles.
//
// image: (B=2, H=128, W=128, D=128, C=4) f32
// transformation: (B=2, 128, 128, 128, 3) f32
// out: (B=2, 128, 128, 128, 4) f32

__device__ uint4 g_packed[4 * 1048576];   // (b,sx) x (y,px,z), 67MB

__device__ __forceinline__ unsigned pack2(float a, float b) {
    __half2 h = __floats2half2_rn(a, b);
    return *reinterpret_cast<unsigned*>(&h);
}
__device__ __forceinline__ float2 up2(unsigned u) {
    __half2 h = *reinterpret_cast<__half2*>(&u);
    return __half22float2(h);
}

// one block per (b,y,px); 128 threads = z
__global__ __launch_bounds__(128) void repack_kernel(const float4* __restrict__ img)
{
    int z  = threadIdx.x;
    int bk = blockIdx.x;
    int px = bk & 63;
    int y  = (bk >> 6) & 127;
    int b  = bk >> 13;

    const float4* imgb = img + (size_t)b * 2097152;
    int x0 = 2 * px;

    // evict-first reads: don't let the f32 image displace packed in L2
    float4 v0 = __ldcs(&imgb[(y << 14) | (x0 << 7) | z]);
    float4 v1 = __ldcs(&imgb[(y << 14) | ((x0 + 1) << 7) | z]);
    float4 v2 = __ldcs(&imgb[(y << 14) | (min(x0 + 2, 127) << 7) | z]);

    uint4 H0, H1;
    H0.x = pack2(v0.x, v0.y);  H0.y = pack2(v0.z, v0.w);
    H0.z = pack2(v1.x, v1.y);  H0.w = pack2(v1.z, v1.w);
    H1.x = pack2(v1.x, v1.y);  H1.y = pack2(v1.z, v1.w);
    H1.z = pack2(v2.x, v2.y);  H1.w = pack2(v2.z, v2.w);

    int base = (y << 13) | (px << 7) | z;
    // default write-back stores: dirty lines stay resident in L2
    g_packed[(((b << 1) | 0) << 20) | base] = H0;
    g_packed[(((b << 1) | 1) << 20) | base] = H1;
}

__global__ __launch_bounds__(256, 6) void st3d_kernel(
    const float* __restrict__ trans,
    float* __restrict__ out)
{
    int t = blockIdx.x * blockDim.x + threadIdx.x;

    int hs = t & 1;          // z-corner select: 0 -> z0, 1 -> z1
    int q  = t >> 1;         // voxel-pair index: voxels v0 = 2q, v0+1
    int v0 = q << 1;

    // v0 = ((b*128 + i)*128 + j)*128 + k0, k0 even -> pair shares b,i,j
    int k0 = v0 & 127;
    int j  = (v0 >> 7) & 127;
    int i  = (v0 >> 14) & 127;
    int b  = v0 >> 21;

    const float step = 2.0f / 127.0f;
    float xl  = -1.0f + (float)j * step;
    float yl  = -1.0f + (float)i * step;
    float zlA = -1.0f + (float)k0 * step;
    float zlB = zlA + step;

    // 6 transform floats for the voxel pair (streaming: don't pollute L2)
    const float2* tp = reinterpret_cast<const float2*>(trans) + (size_t)q * 3;
    float2 fa = __ldcs(&tp[0]);   // txA, tyA
    float2 fb = __ldcs(&tp[1]);   // tzA, txB
    float2 fc = __ldcs(&tp[2]);   // tyB, tzB

    // ---- voxel A setup ----
    float xA = 0.5f * (fa.x * xl + 1.0f) * 128.0f;
    float yA = 0.5f * (fa.y * yl + 1.0f) * 128.0f;
    float zA = 0.5f * (fb.x * zlA + 1.0f) * 128.0f;

    int x0A = min(max((int)floorf(xA), 0), 127);
    int y0A = (int)floorf(yA);
    int z0A = min(max((int)floorf(zA), 0), 127);
    int x1A = min(x0A + 1, 127);
    int y1A = min(max(y0A + 1, 0), 127);
    int z1A = min(z0A + 1, 127);
    y0A = min(max(y0A, 0), 127);

    float dxA = (float)x1A - xA, dyA = (float)y1A - yA, dzA = (float)z1A - zA;
    int   ziA = hs ? z1A : z0A;
    float wzA = hs ? (1.0f - dzA) : dzA;

    int baseA = (((b << 1) | (x0A & 1)) << 20) | ((x0A >> 1) << 7) | ziA;

    // ---- voxel B setup ----
    float xB = 0.5f * (fb.y * xl + 1.0f) * 128.0f;
    float yB = 0.5f * (fc.x * yl + 1.0f) * 128.0f;
    float zB = 0.5f * (fc.y * zlB + 1.0f) * 128.0f;

    int x0B = min(max((int)floorf(xB), 0), 127);
    int y0B = (int)floorf(yB);
    int z0B = min(max((int)floorf(zB), 0), 127);
    int x1B = min(x0B + 1, 127);
    int y1B = min(max(y0B + 1, 0), 127);
    int z1B = min(z0B + 1, 127);
    y0B = min(max(y0B, 0), 127);

    float dxB = (float)x1B - xB, dyB = (float)y1B - yB, dzB = (float)z1B - zB;
    int   ziB = hs ? z1B : z0B;
    float wzB = hs ? (1.0f - dzB) : dzB;

    int baseB = (((b << 1) | (x0B & 1)) << 20) | ((x0B >> 1) << 7) | ziB;

    // ---- issue all 4 gathers back-to-back (pair lanes share lines) ----
    uint4 hA0 = g_packed[baseA | (y0A << 13)];
    uint4 hA1 = g_packed[baseA | (y1A << 13)];
    uint4 hB0 = g_packed[baseB | (y0B << 13)];
    uint4 hB1 = g_packed[baseB | (y1B << 13)];

    float4 rA, rB;
    // ---- voxel A blend (this lane's z-corner) ----
    {
        float wy0 = wzA * dyA, wy1 = wzA * (1.0f - dyA);
        float ex  = 1.0f - dxA;

        float2 a0c01 = up2(hA0.x), a0c23 = up2(hA0.y);  // y0: x0 voxel
        float2 a1c01 = up2(hA0.z), a1c23 = up2(hA0.w);  // y0: x1 voxel
        float2 b0c01 = up2(hA1.x), b0c23 = up2(hA1.y);  // y1: x0 voxel
        float2 b1c01 = up2(hA1.z), b1c23 = up2(hA1.w);  // y1: x1 voxel

        rA.x = wy0 * (dxA * a0c01.x + ex * a1c01.x) + wy1 * (dxA * b0c01.x + ex * b1c01.x);
        rA.y = wy0 * (dxA * a0c01.y + ex * a1c01.y) + wy1 * (dxA * b0c01.y + ex * b1c01.y);
        rA.z = wy0 * (dxA * a0c23.x + ex * a1c23.x) + wy1 * (dxA * b0c23.x + ex * b1c23.x);
        rA.w = wy0 * (dxA * a0c23.y + ex * a1c23.y) + wy1 * (dxA * b0c23.y + ex * b1c23.y);
    }
    // ---- voxel B blend ----
    {
        float wy0 = wzB * dyB, wy1 = wzB * (1.0f - dyB);
        float ex  = 1.0f - dxB;

        float2 a0c01 = up2(hB0.x), a0c23 = up2(hB0.y);
        float2 a1c01 = up2(hB0.z), a1c23 = up2(hB0.w);
        float2 b0c01 = up2(hB1.x), b0c23 = up2(hB1.y);
        float2 b1c01 = up2(hB1.z), b1c23 = up2(hB1.w);

        rB.x = wy0 * (dxB * a0c01.x + ex * a1c01.x) + wy1 * (dxB * b0c01.x + ex * b1c01.x);
        rB.y = wy0 * (dxB * a0c01.y + ex * a1c01.y) + wy1 * (dxB * b0c01.y + ex * b1c01.y);
        rB.z = wy0 * (dxB * a0c23.x + ex * a1c23.x) + wy1 * (dxB * b0c23.x + ex * b1c23.x);
        rB.w = wy0 * (dxB * a0c23.y + ex * a1c23.y) + wy1 * (dxB * b0c23.y + ex * b1c23.y);
    }

    // combine z halves across the lane pair (both voxels)
    rA.x += __shfl_xor_sync(0xffffffffu, rA.x, 1);
    rA.y += __shfl_xor_sync(0xffffffffu, rA.y, 1);
    rA.z += __shfl_xor_sync(0xffffffffu, rA.z, 1);
    rA.w += __shfl_xor_sync(0xffffffffu, rA.w, 1);
    rB.x += __shfl_xor_sync(0xffffffffu, rB.x, 1);
    rB.y += __shfl_xor_sync(0xffffffffu, rB.y, 1);
    rB.z += __shfl_xor_sync(0xffffffffu, rB.z, 1);
    rB.w += __shfl_xor_sync(0xffffffffu, rB.w, 1);

    // even lane stores voxel v0, odd lane stores v0+1 -> dense streaming store
    float4 r = hs ? rB : rA;
    __stcs(reinterpret_cast<float4*>(out) + v0 + hs, r);
}

extern "C" void kernel_launch(void* const* d_in, const int* in_sizes, int n_in,
                              void* d_out, int out_size)
{
    const float* img = (const float*)d_in[0];
    const float* trans = (const float*)d_in[1];
    float* out = (float*)d_out;

    // prepass: 2 x-parity copies of fp16 x-pair patches (67MB)
    repack_kernel<<<2 * 128 * 64, 128>>>(reinterpret_cast<const float4*>(img));

    int total_threads = out_size / 4;
    st3d_kernel<<<total_threads / 256, 256>>>(trans, out);
}

// round 16
// speedup vs baseline: 1.4341x; 1.4341x over previous
#include <cuda_runtime.h>
#include <cuda_fp16.h>

// SpatialTransformer3D: batched 3D trilinear sampling.  (Final: R11 config.)
//
// Prepass packs the image into fp16 x-pair patches, 2 parity copies:
//   patch(b,sx,y,px,z) = { img[y, 2px+sx, z], img[y, min(2px+sx+1,127), z] }
//   = 8 halves = 16B. Packed total 67MB.
// Main kernel: lane bit0 = z-corner select; pair lanes load patches at
// z0 / z0+1 (16B apart -> same 128B line) -> 2 distinct 128B lines per
// voxel (minimal for <=67MB packing). trans/out use streaming hints so
// the packed array keeps L2. Serial schedule; default launch bounds
// (5 CTAs/SM is the measured optimum: 4 -> worse [R8], 6 -> much worse [R15]).
//
// image: (B=2, H=128, W=128, D=128, C=4) f32
// transformation: (B=2, 128, 128, 128, 3) f32
// out: (B=2, 128, 128, 128, 4) f32

__device__ uint4 g_packed[4 * 1048576];   // (b,sx) x (y,px,z), 67MB

__device__ __forceinline__ unsigned pack2(float a, float b) {
    __half2 h = __floats2half2_rn(a, b);
    return *reinterpret_cast<unsigned*>(&h);
}
__device__ __forceinline__ float2 up2(unsigned u) {
    __half2 h = *reinterpret_cast<__half2*>(&u);
    return __half22float2(h);
}

// one block per (b,y,px); 128 threads = z
__global__ __launch_bounds__(128) void repack_kernel(const float4* __restrict__ img)
{
    int z  = threadIdx.x;
    int bk = blockIdx.x;
    int px = bk & 63;
    int y  = (bk >> 6) & 127;
    int b  = bk >> 13;

    const float4* imgb = img + (size_t)b * 2097152;
    int x0 = 2 * px;

    // evict-first reads: don't let the f32 image displace packed in L2
    float4 v0 = __ldcs(&imgb[(y << 14) | (x0 << 7) | z]);
    float4 v1 = __ldcs(&imgb[(y << 14) | ((x0 + 1) << 7) | z]);
    float4 v2 = __ldcs(&imgb[(y << 14) | (min(x0 + 2, 127) << 7) | z]);

    uint4 H0, H1;
    H0.x = pack2(v0.x, v0.y);  H0.y = pack2(v0.z, v0.w);
    H0.z = pack2(v1.x, v1.y);  H0.w = pack2(v1.z, v1.w);
    H1.x = pack2(v1.x, v1.y);  H1.y = pack2(v1.z, v1.w);
    H1.z = pack2(v2.x, v2.y);  H1.w = pack2(v2.z, v2.w);

    int base = (y << 13) | (px << 7) | z;
    // default write-back stores: dirty lines stay resident in L2
    g_packed[(((b << 1) | 0) << 20) | base] = H0;
    g_packed[(((b << 1) | 1) << 20) | base] = H1;
}

__global__ __launch_bounds__(256) void st3d_kernel(
    const float* __restrict__ trans,
    float* __restrict__ out)
{
    int t = blockIdx.x * blockDim.x + threadIdx.x;

    int hs = t & 1;          // z-corner select: 0 -> z0, 1 -> z1
    int q  = t >> 1;         // voxel-pair index: voxels v0 = 2q, v0+1
    int v0 = q << 1;

    // v0 = ((b*128 + i)*128 + j)*128 + k0, k0 even -> pair shares b,i,j
    int k0 = v0 & 127;
    int j  = (v0 >> 7) & 127;
    int i  = (v0 >> 14) & 127;
    int b  = v0 >> 21;

    const float step = 2.0f / 127.0f;
    float xl  = -1.0f + (float)j * step;
    float yl  = -1.0f + (float)i * step;
    float zlA = -1.0f + (float)k0 * step;
    float zlB = zlA + step;

    // 6 transform floats for the voxel pair (streaming: don't pollute L2)
    const float2* tp = reinterpret_cast<const float2*>(trans) + (size_t)q * 3;
    float2 fa = __ldcs(&tp[0]);   // txA, tyA
    float2 fb = __ldcs(&tp[1]);   // tzA, txB
    float2 fc = __ldcs(&tp[2]);   // tyB, tzB

    // ---- voxel A setup ----
    float xA = 0.5f * (fa.x * xl + 1.0f) * 128.0f;
    float yA = 0.5f * (fa.y * yl + 1.0f) * 128.0f;
    float zA = 0.5f * (fb.x * zlA + 1.0f) * 128.0f;

    int x0A = min(max((int)floorf(xA), 0), 127);
    int y0A = (int)floorf(yA);
    int z0A = min(max((int)floorf(zA), 0), 127);
    int x1A = min(x0A + 1, 127);
    int y1A = min(max(y0A + 1, 0), 127);
    int z1A = min(z0A + 1, 127);
    y0A = min(max(y0A, 0), 127);

    float dxA = (float)x1A - xA, dyA = (float)y1A - yA, dzA = (float)z1A - zA;
    int   ziA = hs ? z1A : z0A;
    float wzA = hs ? (1.0f - dzA) : dzA;

    int baseA = (((b << 1) | (x0A & 1)) << 20) | ((x0A >> 1) << 7) | ziA;

    // ---- voxel B setup ----
    float xB = 0.5f * (fb.y * xl + 1.0f) * 128.0f;
    float yB = 0.5f * (fc.x * yl + 1.0f) * 128.0f;
    float zB = 0.5f * (fc.y * zlB + 1.0f) * 128.0f;

    int x0B = min(max((int)floorf(xB), 0), 127);
    int y0B = (int)floorf(yB);
    int z0B = min(max((int)floorf(zB), 0), 127);
    int x1B = min(x0B + 1, 127);
    int y1B = min(max(y0B + 1, 0), 127);
    int z1B = min(z0B + 1, 127);
    y0B = min(max(y0B, 0), 127);

    float dxB = (float)x1B - xB, dyB = (float)y1B - yB, dzB = (float)z1B - zB;
    int   ziB = hs ? z1B : z0B;
    float wzB = hs ? (1.0f - dzB) : dzB;

    int baseB = (((b << 1) | (x0B & 1)) << 20) | ((x0B >> 1) << 7) | ziB;

    // ---- issue all 4 gathers back-to-back (pair lanes share lines) ----
    uint4 hA0 = g_packed[baseA | (y0A << 13)];
    uint4 hA1 = g_packed[baseA | (y1A << 13)];
    uint4 hB0 = g_packed[baseB | (y0B << 13)];
    uint4 hB1 = g_packed[baseB | (y1B << 13)];

    float4 rA, rB;
    // ---- voxel A blend (this lane's z-corner) ----
    {
        float wy0 = wzA * dyA, wy1 = wzA * (1.0f - dyA);
        float ex  = 1.0f - dxA;

        float2 a0c01 = up2(hA0.x), a0c23 = up2(hA0.y);  // y0: x0 voxel
        float2 a1c01 = up2(hA0.z), a1c23 = up2(hA0.w);  // y0: x1 voxel
        float2 b0c01 = up2(hA1.x), b0c23 = up2(hA1.y);  // y1: x0 voxel
        float2 b1c01 = up2(hA1.z), b1c23 = up2(hA1.w);  // y1: x1 voxel

        rA.x = wy0 * (dxA * a0c01.x + ex * a1c01.x) + wy1 * (dxA * b0c01.x + ex * b1c01.x);
        rA.y = wy0 * (dxA * a0c01.y + ex * a1c01.y) + wy1 * (dxA * b0c01.y + ex * b1c01.y);
        rA.z = wy0 * (dxA * a0c23.x + ex * a1c23.x) + wy1 * (dxA * b0c23.x + ex * b1c23.x);
        rA.w = wy0 * (dxA * a0c23.y + ex * a1c23.y) + wy1 * (dxA * b0c23.y + ex * b1c23.y);
    }
    // ---- voxel B blend ----
    {
        float wy0 = wzB * dyB, wy1 = wzB * (1.0f - dyB);
        float ex  = 1.0f - dxB;

        float2 a0c01 = up2(hB0.x), a0c23 = up2(hB0.y);
        float2 a1c01 = up2(hB0.z), a1c23 = up2(hB0.w);
        float2 b0c01 = up2(hB1.x), b0c23 = up2(hB1.y);
        float2 b1c01 = up2(hB1.z), b1c23 = up2(hB1.w);

        rB.x = wy0 * (dxB * a0c01.x + ex * a1c01.x) + wy1 * (dxB * b0c01.x + ex * b1c01.x);
        rB.y = wy0 * (dxB * a0c01.y + ex * a1c01.y) + wy1 * (dxB * b0c01.y + ex * b1c01.y);
        rB.z = wy0 * (dxB * a0c23.x + ex * a1c23.x) + wy1 * (dxB * b0c23.x + ex * b1c23.x);
        rB.w = wy0 * (dxB * a0c23.y + ex * a1c23.y) + wy1 * (dxB * b0c23.y + ex * b1c23.y);
    }

    // combine z halves across the lane pair (both voxels)
    rA.x += __shfl_xor_sync(0xffffffffu, rA.x, 1);
    rA.y += __shfl_xor_sync(0xffffffffu, rA.y, 1);
    rA.z += __shfl_xor_sync(0xffffffffu, rA.z, 1);
    rA.w += __shfl_xor_sync(0xffffffffu, rA.w, 1);
    rB.x += __shfl_xor_sync(0xffffffffu, rB.x, 1);
    rB.y += __shfl_xor_sync(0xffffffffu, rB.y, 1);
    rB.z += __shfl_xor_sync(0xffffffffu, rB.z, 1);
    rB.w += __shfl_xor_sync(0xffffffffu, rB.w, 1);

    // even lane stores voxel v0, odd lane stores v0+1 -> dense streaming store
    float4 r = hs ? rB : rA;
    __stcs(reinterpret_cast<float4*>(out) + v0 + hs, r);
}

extern "C" void kernel_launch(void* const* d_in, const int* in_sizes, int n_in,
                              void* d_out, int out_size)
{
    const float* img = (const float*)d_in[0];
    const float* trans = (const float*)d_in[1];
    float* out = (float*)d_out;

    // prepass: 2 x-parity copies of fp16 x-pair patches (67MB)
    repack_kernel<<<2 * 128 * 64, 128>>>(reinterpret_cast<const float4*>(img));

    int total_threads = out_size / 4;
    st3d_kernel<<<total_threads / 256, 256>>>(trans, out);
}